// round 1
// baseline (speedup 1.0000x reference)
#include <cuda_runtime.h>
#include <cuda_bf16.h>
#include <math.h>

// Problem constants
#define BATCH 2
#define SEQ   2048
#define EMB   1024
#define NH    16
#define NKV   4
#define HD    64
#define KVDIM 256           // NKV * HD
#define ROWS  (BATCH*SEQ)   // 4096

// ---------------- scratch (no allocations allowed) ----------------
__device__ float g_Q[ROWS * EMB];    // 16 MB
__device__ float g_K[ROWS * KVDIM];  //  4 MB
__device__ float g_V[ROWS * KVDIM];  //  4 MB
__device__ float g_O[ROWS * EMB];    // 16 MB

// ---------------- 128x128x16 fp32 GEMM, 256 threads, 8x8 microtile ----------------
// C[M,N] = A[M,K] * B[K,N], all row-major. M%128==0, N%128==0, K%16==0 assumed.
__global__ __launch_bounds__(256) void sgemm128(
    const float* __restrict__ A, const float* __restrict__ B,
    float* __restrict__ C, int M, int N, int Kdim)
{
    __shared__ float As[16][128];   // transposed A tile: As[k][m]
    __shared__ float Bs[16][128];   // Bs[k][n]

    const int bx = blockIdx.x;   // N tile
    const int by = blockIdx.y;   // M tile
    const int tid = threadIdx.x;
    const int tx = tid % 16;     // 16 thread-cols * 8 = 128
    const int ty = tid / 16;     // 16 thread-rows * 8 = 128

    const float* Ab = A + (size_t)by * 128 * Kdim;
    const float* Bb = B + (size_t)bx * 128;

    float acc[8][8];
#pragma unroll
    for (int i = 0; i < 8; i++)
#pragma unroll
        for (int j = 0; j < 8; j++) acc[i][j] = 0.0f;

    // A tile load mapping: 128 rows x 16 cols = 512 float4; thread t does 2.
    const int a_row0 = tid / 4;        // 0..63
    const int a_col4 = tid % 4;        // float4 column within 16
    // B tile load mapping: 16 rows x 128 cols = 512 float4; thread t does 2.
    const int b_row0 = tid / 32;       // 0..7
    const int b_col4 = tid % 32;       // float4 column within 128

    for (int k0 = 0; k0 < Kdim; k0 += 16) {
        // load A (transpose into As)
#pragma unroll
        for (int p = 0; p < 2; p++) {
            int row = a_row0 + p * 64;
            float4 a = *(const float4*)(Ab + (size_t)row * Kdim + k0 + a_col4 * 4);
            As[a_col4 * 4 + 0][row] = a.x;
            As[a_col4 * 4 + 1][row] = a.y;
            As[a_col4 * 4 + 2][row] = a.z;
            As[a_col4 * 4 + 3][row] = a.w;
        }
        // load B
#pragma unroll
        for (int p = 0; p < 2; p++) {
            int row = b_row0 + p * 8;
            float4 bv = *(const float4*)(Bb + (size_t)(k0 + row) * N + b_col4 * 4);
            *(float4*)(&Bs[row][b_col4 * 4]) = bv;
        }
        __syncthreads();

#pragma unroll
        for (int k = 0; k < 16; k++) {
            float a[8], b[8];
#pragma unroll
            for (int i = 0; i < 4; i++) a[i]     = As[k][ty * 8 + i];
#pragma unroll
            for (int i = 0; i < 4; i++) a[i + 4] = As[k][ty * 8 + 4 + i];
#pragma unroll
            for (int j = 0; j < 4; j++) b[j]     = Bs[k][tx * 8 + j];
#pragma unroll
            for (int j = 0; j < 4; j++) b[j + 4] = Bs[k][tx * 8 + 4 + j];
#pragma unroll
            for (int i = 0; i < 8; i++)
#pragma unroll
                for (int j = 0; j < 8; j++)
                    acc[i][j] = fmaf(a[i], b[j], acc[i][j]);
        }
        __syncthreads();
    }

    // write back (float4 x2 per row)
#pragma unroll
    for (int i = 0; i < 8; i++) {
        float* Crow = C + (size_t)(by * 128 + ty * 8 + i) * N + bx * 128 + tx * 8;
        float4 v0 = make_float4(acc[i][0], acc[i][1], acc[i][2], acc[i][3]);
        float4 v1 = make_float4(acc[i][4], acc[i][5], acc[i][6], acc[i][7]);
        *(float4*)(Crow + 0) = v0;
        *(float4*)(Crow + 4) = v1;
    }
}

// ---------------- flash attention (causal, GQA), fp32 ----------------
// grid: (SEQ/128, NH, BATCH), block: 128 threads; each thread owns one query row.
__global__ __launch_bounds__(128) void flash_attn(
    const float* __restrict__ Q, const float* __restrict__ K,
    const float* __restrict__ V, float* __restrict__ O)
{
    __shared__ float Ks[32][64];
    __shared__ float Vs[32][64];

    const int qb  = blockIdx.x;
    const int h   = blockIdx.y;
    const int b   = blockIdx.z;
    const int g   = h / (NH / NKV);     // kv head
    const int tid = threadIdx.x;
    const int qi  = qb * 128 + tid;     // query position in sequence
    const size_t qrow = (size_t)b * SEQ + qi;
    const float inv_sqrt_d = 0.125f;    // 1/sqrt(64)

    // load q into registers, pre-scaled
    float q[HD];
#pragma unroll
    for (int d = 0; d < HD; d += 4) {
        float4 v = *(const float4*)(Q + qrow * EMB + h * HD + d);
        q[d + 0] = v.x * inv_sqrt_d;
        q[d + 1] = v.y * inv_sqrt_d;
        q[d + 2] = v.z * inv_sqrt_d;
        q[d + 3] = v.w * inv_sqrt_d;
    }

    float acc[HD];
#pragma unroll
    for (int d = 0; d < HD; d++) acc[d] = 0.0f;
    float m = -INFINITY, l = 0.0f;

    const int nkt = qb * 4 + 4;         // key tiles of 32 needed (causal)
    for (int kt = 0; kt < nkt; kt++) {
        // cooperative load of K,V tile: 32 keys x 64 dims, 4 float4 per thread each
#pragma unroll
        for (int p = 0; p < 4; p++) {
            int idx  = tid + p * 128;       // float4 index 0..511
            int row  = idx / 16;            // key within tile
            int col4 = idx % 16;
            size_t krow = (size_t)b * SEQ + kt * 32 + row;
            *(float4*)(&Ks[row][col4 * 4]) =
                *(const float4*)(K + krow * KVDIM + g * HD + col4 * 4);
            *(float4*)(&Vs[row][col4 * 4]) =
                *(const float4*)(V + krow * KVDIM + g * HD + col4 * 4);
        }
        __syncthreads();

        // scores for this thread's query row
        float s[32];
        float mx = m;
#pragma unroll
        for (int j = 0; j < 32; j++) {
            float sum = 0.0f;
#pragma unroll
            for (int d = 0; d < HD; d++) sum = fmaf(q[d], Ks[j][d], sum);
            int kidx = kt * 32 + j;
            s[j] = (kidx <= qi) ? sum : -INFINITY;
            mx = fmaxf(mx, s[j]);
        }

        const float scale = __expf(m - mx);
        l *= scale;
#pragma unroll
        for (int d = 0; d < HD; d++) acc[d] *= scale;

#pragma unroll
        for (int j = 0; j < 32; j++) {
            float p = __expf(s[j] - mx);
            l += p;
#pragma unroll
            for (int d = 0; d < HD; d++) acc[d] = fmaf(p, Vs[j][d], acc[d]);
        }
        m = mx;
        __syncthreads();
    }

    const float inv_l = 1.0f / l;
#pragma unroll
    for (int d = 0; d < HD; d += 4) {
        float4 v = make_float4(acc[d] * inv_l, acc[d + 1] * inv_l,
                               acc[d + 2] * inv_l, acc[d + 3] * inv_l);
        *(float4*)(O + qrow * EMB + h * HD + d) = v;
    }
}

// ---------------- launch ----------------
extern "C" void kernel_launch(void* const* d_in, const int* in_sizes, int n_in,
                              void* d_out, int out_size)
{
    const float* x  = (const float*)d_in[0];
    const float* Wq = (const float*)d_in[1];
    const float* Wk = (const float*)d_in[2];
    const float* Wv = (const float*)d_in[3];
    const float* Wo = (const float*)d_in[4];
    float* out = (float*)d_out;

    float *Q, *K, *V, *O;
    cudaGetSymbolAddress((void**)&Q, g_Q);
    cudaGetSymbolAddress((void**)&K, g_K);
    cudaGetSymbolAddress((void**)&V, g_V);
    cudaGetSymbolAddress((void**)&O, g_O);

    // projections
    sgemm128<<<dim3(EMB / 128, ROWS / 128), 256>>>(x, Wq, Q, ROWS, EMB, EMB);
    sgemm128<<<dim3(KVDIM / 128, ROWS / 128), 256>>>(x, Wk, K, ROWS, KVDIM, EMB);
    sgemm128<<<dim3(KVDIM / 128, ROWS / 128), 256>>>(x, Wv, V, ROWS, KVDIM, EMB);

    // attention
    flash_attn<<<dim3(SEQ / 128, NH, BATCH), 128>>>(Q, K, V, O);

    // output projection
    sgemm128<<<dim3(EMB / 128, ROWS / 128), 256>>>(O, Wo, out, ROWS, EMB, EMB);
}

// round 3
// speedup vs baseline: 1.3258x; 1.3258x over previous
#include <cuda_runtime.h>
#include <cuda_bf16.h>
#include <math.h>
#include <cstdint>

// Problem constants
#define BATCH 2
#define SEQ   2048
#define EMB   1024
#define NH    16
#define NKV   4
#define HD    64
#define KVDIM 256
#define ROWS  (BATCH*SEQ)     // 4096
#define K3    (3*EMB)         // 3072 : [Ah | Ah | Al] x [Bh | Bl | Bh]
#define QKVW  (EMB + 2*KVDIM) // 1536 fused QKV output width

// ---------------- scratch ----------------
__device__ float g_QKV[ROWS * QKVW];            // fused projection output
__device__ float g_O[ROWS * EMB];               // attention output
__device__ __nv_bfloat16 g_A   [ROWS * K3];     // split activations (x, later O)
__device__ __nv_bfloat16 g_Bqkv[QKVW * K3];     // split+transposed fused QKV weights
__device__ __nv_bfloat16 g_Bo  [EMB  * K3];     // split+transposed Wo

// ---------------- helpers ----------------
__device__ __forceinline__ uint32_t smem_u32(const void* p) {
    uint32_t a;
    asm("{ .reg .u64 t; cvta.to.shared.u64 t, %1; cvt.u32.u64 %0, t; }" : "=r"(a) : "l"(p));
    return a;
}
__device__ __forceinline__ void ldsm_x4(uint32_t* r, uint32_t addr) {
    asm volatile("ldmatrix.sync.aligned.m8n8.x4.shared.b16 {%0,%1,%2,%3}, [%4];"
        : "=r"(r[0]), "=r"(r[1]), "=r"(r[2]), "=r"(r[3]) : "r"(addr));
}
__device__ __forceinline__ void ldsm_x2(uint32_t* r, uint32_t addr) {
    asm volatile("ldmatrix.sync.aligned.m8n8.x2.shared.b16 {%0,%1}, [%2];"
        : "=r"(r[0]), "=r"(r[1]) : "r"(addr));
}
__device__ __forceinline__ void mma16816(float* c, const uint32_t* a, const uint32_t* b) {
    asm volatile("mma.sync.aligned.m16n8k16.row.col.f32.bf16.bf16.f32 "
        "{%0,%1,%2,%3}, {%4,%5,%6,%7}, {%8,%9}, {%0,%1,%2,%3};"
        : "+f"(c[0]), "+f"(c[1]), "+f"(c[2]), "+f"(c[3])
        : "r"(a[0]), "r"(a[1]), "r"(a[2]), "r"(a[3]), "r"(b[0]), "r"(b[1]));
}

// ---------------- split-precision conversion kernels ----------------
// X [M,1024] fp32 -> A [M, 3072] bf16 : [hi | hi | lo]
__global__ __launch_bounds__(256) void conv_split_A(const float* __restrict__ X,
                                                    __nv_bfloat16* __restrict__ A)
{
    int idx = blockIdx.x * 256 + threadIdx.x;   // over M*1024
    int r = idx >> 10, c = idx & 1023;
    float v = X[idx];
    __nv_bfloat16 h = __float2bfloat16(v);
    __nv_bfloat16 l = __float2bfloat16(v - __bfloat162float(h));
    size_t base = (size_t)r * K3;
    A[base + c] = h;
    A[base + 1024 + c] = h;
    A[base + 2048 + c] = l;
}
// W [1024, N] fp32 -> Bt [N, 3072] bf16 : rows n, cols [hi | lo | hi] (transposed)
__global__ __launch_bounds__(256) void conv_split_Bt(const float* __restrict__ W,
                                                     __nv_bfloat16* __restrict__ Bt, int N)
{
    int idx = blockIdx.x * 256 + threadIdx.x;   // over N*1024
    int n = idx >> 10, k = idx & 1023;
    float v = W[(size_t)k * N + n];
    __nv_bfloat16 h = __float2bfloat16(v);
    __nv_bfloat16 l = __float2bfloat16(v - __bfloat162float(h));
    size_t base = (size_t)n * K3;
    Bt[base + k] = h;
    Bt[base + 1024 + k] = l;
    Bt[base + 2048 + k] = h;
}

// ---------------- HMMA bf16 GEMM: C[M,N] = A[M,K3] * Bt[N,K3]^T ----------------
// CTA tile 128x128, BK=64, 256 threads = 8 warps (2 x 4), warp tile 64x32.
__global__ __launch_bounds__(256) void gemm_bf16(
    const __nv_bfloat16* __restrict__ A,
    const __nv_bfloat16* __restrict__ Bt,
    float* __restrict__ C, int N)
{
    __shared__ __align__(128) char sA[128 * 64 * 2];  // 16 KB, SW128 swizzled
    __shared__ __align__(128) char sB[128 * 64 * 2];  // 16 KB

    const int tid  = threadIdx.x;
    const int lane = tid & 31, wid = tid >> 5;
    const int wm = wid & 1;         // 0..1  (64-row slice)
    const int wn = wid >> 1;        // 0..3  (32-col slice)
    const int bx = blockIdx.x, by = blockIdx.y;

    const __nv_bfloat16* Ab = A  + (size_t)by * 128 * K3;
    const __nv_bfloat16* Bb = Bt + (size_t)bx * 128 * K3;
    const uint32_t sA_u = smem_u32(sA);
    const uint32_t sB_u = smem_u32(sB);

    float acc[4][4][4];
#pragma unroll
    for (int i = 0; i < 4; i++)
#pragma unroll
        for (int j = 0; j < 4; j++)
#pragma unroll
            for (int q = 0; q < 4; q++) acc[i][j][q] = 0.0f;

    // ldmatrix per-lane address components (row, 16B-chunk), swizzle applied per use
    const int a_r = wm * 64 + (lane & 15);     // + i*16
    const int a_c = (lane >> 4);               // + ks*2
    const int b_r = wn * 32 + (lane & 7);      // + j*8
    const int b_c = ((lane >> 3) & 1);         // + ks*2

    for (int ch = 0; ch < K3 / 64; ch++) {
        const int k0 = ch * 64;
        // gmem -> smem : 128 rows x 64 bf16 (128B rows), 4 uint4 per thread each
#pragma unroll
        for (int p = 0; p < 4; p++) {
            int idx = p * 256 + tid;           // 0..1023 uint4 slots
            int row = idx >> 3, c16 = idx & 7;
            uint32_t sw = row * 128 + ((c16 ^ (row & 7)) * 16);
            *(uint4*)(sA + sw) = *(const uint4*)(Ab + (size_t)row * K3 + k0 + c16 * 8);
            *(uint4*)(sB + sw) = *(const uint4*)(Bb + (size_t)row * K3 + k0 + c16 * 8);
        }
        __syncthreads();

#pragma unroll
        for (int ks = 0; ks < 4; ks++) {
            uint32_t a[4][4], b[4][2];
#pragma unroll
            for (int i = 0; i < 4; i++) {
                int row = a_r + i * 16;
                int chk = a_c + ks * 2;
                ldsm_x4(a[i], sA_u + row * 128 + ((chk ^ (row & 7)) * 16));
            }
#pragma unroll
            for (int j = 0; j < 4; j++) {
                int row = b_r + j * 8;
                int chk = b_c + ks * 2;
                ldsm_x2(b[j], sB_u + row * 128 + ((chk ^ (row & 7)) * 16));
            }
#pragma unroll
            for (int i = 0; i < 4; i++)
#pragma unroll
                for (int j = 0; j < 4; j++)
                    mma16816(acc[i][j], a[i], b[j]);
        }
        __syncthreads();
    }

    // epilogue: direct stores (c0,c1 @ row g, c2,c3 @ row g+8; cols (lane%4)*2)
#pragma unroll
    for (int i = 0; i < 4; i++)
#pragma unroll
        for (int j = 0; j < 4; j++) {
            int r0  = by * 128 + wm * 64 + i * 16 + (lane >> 2);
            int col = bx * 128 + wn * 32 + j * 8 + (lane & 3) * 2;
            float* p0 = C + (size_t)r0 * N + col;
            p0[0] = acc[i][j][0]; p0[1] = acc[i][j][1];
            float* p1 = p0 + (size_t)8 * N;
            p1[0] = acc[i][j][2]; p1[1] = acc[i][j][3];
        }
}

// ---------------- flash attention (causal, GQA), fp32 ----------------
// reads fused QKV [ROWS, 1536]: Q at col h*64, K at 1024+g*64, V at 1280+g*64
__global__ __launch_bounds__(128) void flash_attn(
    const float* __restrict__ QKV, float* __restrict__ O)
{
    __shared__ float Ks[32][64];
    __shared__ float Vs[32][64];

    const int qb  = blockIdx.x;
    const int h   = blockIdx.y;
    const int b   = blockIdx.z;
    const int g   = h / (NH / NKV);
    const int tid = threadIdx.x;
    const int qi  = qb * 128 + tid;
    const size_t qrow = (size_t)b * SEQ + qi;
    const float inv_sqrt_d = 0.125f;

    float q[HD];
#pragma unroll
    for (int d = 0; d < HD; d += 4) {
        float4 v = *(const float4*)(QKV + qrow * QKVW + h * HD + d);
        q[d + 0] = v.x * inv_sqrt_d;
        q[d + 1] = v.y * inv_sqrt_d;
        q[d + 2] = v.z * inv_sqrt_d;
        q[d + 3] = v.w * inv_sqrt_d;
    }

    float acc[HD];
#pragma unroll
    for (int d = 0; d < HD; d++) acc[d] = 0.0f;
    float m = -INFINITY, lsum = 0.0f;

    const int nkt = qb * 4 + 4;
    for (int kt = 0; kt < nkt; kt++) {
#pragma unroll
        for (int p = 0; p < 4; p++) {
            int idx  = tid + p * 128;
            int row  = idx / 16;
            int col4 = idx % 16;
            size_t krow = (size_t)b * SEQ + kt * 32 + row;
            *(float4*)(&Ks[row][col4 * 4]) =
                *(const float4*)(QKV + krow * QKVW + EMB + g * HD + col4 * 4);
            *(float4*)(&Vs[row][col4 * 4]) =
                *(const float4*)(QKV + krow * QKVW + EMB + KVDIM + g * HD + col4 * 4);
        }
        __syncthreads();

        float s[32];
        float mx = m;
#pragma unroll
        for (int j = 0; j < 32; j++) {
            float sum = 0.0f;
#pragma unroll
            for (int d = 0; d < HD; d++) sum = fmaf(q[d], Ks[j][d], sum);
            int kidx = kt * 32 + j;
            s[j] = (kidx <= qi) ? sum : -INFINITY;
            mx = fmaxf(mx, s[j]);
        }

        const float scale = __expf(m - mx);
        lsum *= scale;
#pragma unroll
        for (int d = 0; d < HD; d++) acc[d] *= scale;

#pragma unroll
        for (int j = 0; j < 32; j++) {
            float p = __expf(s[j] - mx);
            lsum += p;
#pragma unroll
            for (int d = 0; d < HD; d++) acc[d] = fmaf(p, Vs[j][d], acc[d]);
        }
        m = mx;
        __syncthreads();
    }

    const float inv_l = 1.0f / lsum;
#pragma unroll
    for (int d = 0; d < HD; d += 4) {
        float4 v = make_float4(acc[d] * inv_l, acc[d + 1] * inv_l,
                               acc[d + 2] * inv_l, acc[d + 3] * inv_l);
        *(float4*)(O + qrow * EMB + h * HD + d) = v;
    }
}

// ---------------- launch ----------------
extern "C" void kernel_launch(void* const* d_in, const int* in_sizes, int n_in,
                              void* d_out, int out_size)
{
    const float* x  = (const float*)d_in[0];
    const float* Wq = (const float*)d_in[1];
    const float* Wk = (const float*)d_in[2];
    const float* Wv = (const float*)d_in[3];
    const float* Wo = (const float*)d_in[4];
    float* out = (float*)d_out;

    float *QKV, *O;
    __nv_bfloat16 *A, *Bqkv, *Bo;
    cudaGetSymbolAddress((void**)&QKV, g_QKV);
    cudaGetSymbolAddress((void**)&O, g_O);
    cudaGetSymbolAddress((void**)&A, g_A);
    cudaGetSymbolAddress((void**)&Bqkv, g_Bqkv);
    cudaGetSymbolAddress((void**)&Bo, g_Bo);

    // split-precision conversions (weights fused into one QKV buffer)
    conv_split_A<<<ROWS * EMB / 256, 256>>>(x, A);
    conv_split_Bt<<<EMB * EMB / 256, 256>>>(Wq, Bqkv, EMB);
    conv_split_Bt<<<EMB * KVDIM / 256, 256>>>(Wk, Bqkv + (size_t)EMB * K3, KVDIM);
    conv_split_Bt<<<EMB * KVDIM / 256, 256>>>(Wv, Bqkv + (size_t)(EMB + KVDIM) * K3, KVDIM);
    conv_split_Bt<<<EMB * EMB / 256, 256>>>(Wo, Bo, EMB);

    // fused QKV projection (tensor cores)
    gemm_bf16<<<dim3(QKVW / 128, ROWS / 128), 256>>>(A, Bqkv, QKV, QKVW);

    // attention (fp32)
    flash_attn<<<dim3(SEQ / 128, NH, BATCH), 128>>>(QKV, O);

    // output projection
    conv_split_A<<<ROWS * EMB / 256, 256>>>(O, A);
    gemm_bf16<<<dim3(EMB / 128, ROWS / 128), 256>>>(A, Bo, out, EMB);
}

// round 4
// speedup vs baseline: 3.5298x; 2.6625x over previous
#include <cuda_runtime.h>
#include <cuda_bf16.h>
#include <math.h>
#include <cstdint>

// Problem constants
#define BATCH 2
#define SEQ   2048
#define EMB   1024
#define NH    16
#define NKV   4
#define HD    64
#define KVDIM 256
#define ROWS  (BATCH*SEQ)     // 4096
#define K3    (3*EMB)         // 3072 : [Ah | Ah | Al] x [Bh | Bl | Bh]
#define QKVW  (EMB + 2*KVDIM) // 1536 fused QKV output width

// flash tiling
#define QT 64
#define KT 64
#define QS_STR 136            // bf16 units per row (272B = 17 x 16B, conflict-free)
#define VS_STR 72             // 144B = 9 x 16B

// ---------------- scratch ----------------
__device__ float g_QKV[ROWS * QKVW];
__device__ float g_O[ROWS * EMB];
__device__ __nv_bfloat16 g_A   [ROWS * K3];
__device__ __nv_bfloat16 g_Bqkv[QKVW * K3];
__device__ __nv_bfloat16 g_Bo  [EMB  * K3];

// ---------------- helpers ----------------
__device__ __forceinline__ uint32_t smem_u32(const void* p) {
    uint32_t a;
    asm("{ .reg .u64 t; cvta.to.shared.u64 t, %1; cvt.u32.u64 %0, t; }" : "=r"(a) : "l"(p));
    return a;
}
__device__ __forceinline__ void ldsm_x4(uint32_t* r, uint32_t addr) {
    asm volatile("ldmatrix.sync.aligned.m8n8.x4.shared.b16 {%0,%1,%2,%3}, [%4];"
        : "=r"(r[0]), "=r"(r[1]), "=r"(r[2]), "=r"(r[3]) : "r"(addr));
}
__device__ __forceinline__ void ldsm_x2(uint32_t* r, uint32_t addr) {
    asm volatile("ldmatrix.sync.aligned.m8n8.x2.shared.b16 {%0,%1}, [%2];"
        : "=r"(r[0]), "=r"(r[1]) : "r"(addr));
}
__device__ __forceinline__ void ldsm_x2t(uint32_t* r, uint32_t addr) {
    asm volatile("ldmatrix.sync.aligned.m8n8.x2.trans.shared.b16 {%0,%1}, [%2];"
        : "=r"(r[0]), "=r"(r[1]) : "r"(addr));
}
__device__ __forceinline__ void mma16816(float* c, const uint32_t* a, const uint32_t* b) {
    asm volatile("mma.sync.aligned.m16n8k16.row.col.f32.bf16.bf16.f32 "
        "{%0,%1,%2,%3}, {%4,%5,%6,%7}, {%8,%9}, {%0,%1,%2,%3};"
        : "+f"(c[0]), "+f"(c[1]), "+f"(c[2]), "+f"(c[3])
        : "r"(a[0]), "r"(a[1]), "r"(a[2]), "r"(a[3]), "r"(b[0]), "r"(b[1]));
}
__device__ __forceinline__ float ex2f(float x) {
    float y;
    asm("ex2.approx.ftz.f32 %0, %1;" : "=f"(y) : "f"(x));
    return y;
}
__device__ __forceinline__ uint32_t pack_bf2(float a, float b) {
    __nv_bfloat162 t = __floats2bfloat162_rn(a, b);   // x = a (low), y = b (high)
    return *(uint32_t*)&t;
}

// ---------------- split-precision conversion kernels ----------------
__global__ __launch_bounds__(256) void conv_split_A(const float* __restrict__ X,
                                                    __nv_bfloat16* __restrict__ A)
{
    int idx = blockIdx.x * 256 + threadIdx.x;
    int r = idx >> 10, c = idx & 1023;
    float v = X[idx];
    __nv_bfloat16 h = __float2bfloat16(v);
    __nv_bfloat16 l = __float2bfloat16(v - __bfloat162float(h));
    size_t base = (size_t)r * K3;
    A[base + c] = h;
    A[base + 1024 + c] = h;
    A[base + 2048 + c] = l;
}
__global__ __launch_bounds__(256) void conv_split_Bt(const float* __restrict__ W,
                                                     __nv_bfloat16* __restrict__ Bt, int N)
{
    int idx = blockIdx.x * 256 + threadIdx.x;
    int n = idx >> 10, k = idx & 1023;
    float v = W[(size_t)k * N + n];
    __nv_bfloat16 h = __float2bfloat16(v);
    __nv_bfloat16 l = __float2bfloat16(v - __bfloat162float(h));
    size_t base = (size_t)n * K3;
    Bt[base + k] = h;
    Bt[base + 1024 + k] = l;
    Bt[base + 2048 + k] = h;
}

// ---------------- HMMA bf16 GEMM (unchanged from R2) ----------------
__global__ __launch_bounds__(256) void gemm_bf16(
    const __nv_bfloat16* __restrict__ A,
    const __nv_bfloat16* __restrict__ Bt,
    float* __restrict__ C, int N)
{
    __shared__ __align__(128) char sA[128 * 64 * 2];
    __shared__ __align__(128) char sB[128 * 64 * 2];

    const int tid  = threadIdx.x;
    const int lane = tid & 31, wid = tid >> 5;
    const int wm = wid & 1;
    const int wn = wid >> 1;
    const int bx = blockIdx.x, by = blockIdx.y;

    const __nv_bfloat16* Ab = A  + (size_t)by * 128 * K3;
    const __nv_bfloat16* Bb = Bt + (size_t)bx * 128 * K3;
    const uint32_t sA_u = smem_u32(sA);
    const uint32_t sB_u = smem_u32(sB);

    float acc[4][4][4];
#pragma unroll
    for (int i = 0; i < 4; i++)
#pragma unroll
        for (int j = 0; j < 4; j++)
#pragma unroll
            for (int q = 0; q < 4; q++) acc[i][j][q] = 0.0f;

    const int a_r = wm * 64 + (lane & 15);
    const int a_c = (lane >> 4);
    const int b_r = wn * 32 + (lane & 7);
    const int b_c = ((lane >> 3) & 1);

    for (int ch = 0; ch < K3 / 64; ch++) {
        const int k0 = ch * 64;
#pragma unroll
        for (int p = 0; p < 4; p++) {
            int idx = p * 256 + tid;
            int row = idx >> 3, c16 = idx & 7;
            uint32_t sw = row * 128 + ((c16 ^ (row & 7)) * 16);
            *(uint4*)(sA + sw) = *(const uint4*)(Ab + (size_t)row * K3 + k0 + c16 * 8);
            *(uint4*)(sB + sw) = *(const uint4*)(Bb + (size_t)row * K3 + k0 + c16 * 8);
        }
        __syncthreads();

#pragma unroll
        for (int ks = 0; ks < 4; ks++) {
            uint32_t a[4][4], b[4][2];
#pragma unroll
            for (int i = 0; i < 4; i++) {
                int row = a_r + i * 16;
                int chk = a_c + ks * 2;
                ldsm_x4(a[i], sA_u + row * 128 + ((chk ^ (row & 7)) * 16));
            }
#pragma unroll
            for (int j = 0; j < 4; j++) {
                int row = b_r + j * 8;
                int chk = b_c + ks * 2;
                ldsm_x2(b[j], sB_u + row * 128 + ((chk ^ (row & 7)) * 16));
            }
#pragma unroll
            for (int i = 0; i < 4; i++)
#pragma unroll
                for (int j = 0; j < 4; j++)
                    mma16816(acc[i][j], a[i], b[j]);
        }
        __syncthreads();
    }

#pragma unroll
    for (int i = 0; i < 4; i++)
#pragma unroll
        for (int j = 0; j < 4; j++) {
            int r0  = by * 128 + wm * 64 + i * 16 + (lane >> 2);
            int col = bx * 128 + wn * 32 + j * 8 + (lane & 3) * 2;
            float* p0 = C + (size_t)r0 * N + col;
            p0[0] = acc[i][j][0]; p0[1] = acc[i][j][1];
            float* p1 = p0 + (size_t)8 * N;
            p1[0] = acc[i][j][2]; p1[1] = acc[i][j][3];
        }
}

// ---------------- HMMA flash attention (causal, GQA, split precision) ----------------
// grid (SEQ/64, NH, BATCH), 128 threads = 4 warps x 16 query rows.
// smem: Qs[64][136] (qh|ql), Ks[64][136] (kh|kl), Vh[64][72], Vl[64][72]
__global__ __launch_bounds__(128) void flash_hmma(
    const float* __restrict__ QKV, float* __restrict__ O)
{
    extern __shared__ __align__(16) char smem[];
    __nv_bfloat16* Qs = (__nv_bfloat16*)smem;                   // 17408 B
    __nv_bfloat16* Ks = (__nv_bfloat16*)(smem + 17408);         // 17408 B
    __nv_bfloat16* Vh = (__nv_bfloat16*)(smem + 34816);         //  9216 B
    __nv_bfloat16* Vl = (__nv_bfloat16*)(smem + 44032);         //  9216 B

    const int qb = blockIdx.x, h = blockIdx.y, b = blockIdx.z;
    const int g = h >> 2;                       // NH/NKV = 4
    const int tid = threadIdx.x, lane = tid & 31, wid = tid >> 5;
    const uint32_t sQ = smem_u32(Qs), sK = smem_u32(Ks);
    const uint32_t sVh = smem_u32(Vh), sVl = smem_u32(Vl);

    const float SCALE = 0.125f * 1.44269504089f;   // 1/sqrt(64) * log2(e)

    // ---- load + split Q tile (scaled) ----
#pragma unroll
    for (int it = 0; it < 8; it++) {
        int row = it * 8 + (tid >> 4);
        int c4  = tid & 15;
        float4 v = *(const float4*)(QKV + (size_t)(b * SEQ + qb * QT + row) * QKVW + h * HD + c4 * 4);
        float f[4] = {v.x * SCALE, v.y * SCALE, v.z * SCALE, v.w * SCALE};
#pragma unroll
        for (int j = 0; j < 4; j++) {
            __nv_bfloat16 hi = __float2bfloat16(f[j]);
            Qs[row * QS_STR + c4 * 4 + j]      = hi;
            Qs[row * QS_STR + 64 + c4 * 4 + j] = __float2bfloat16(f[j] - __bfloat162float(hi));
        }
    }
    __syncthreads();

    float accO[8][4];
#pragma unroll
    for (int n = 0; n < 8; n++)
#pragma unroll
        for (int q = 0; q < 4; q++) accO[n][q] = 0.0f;
    float m0 = -INFINITY, m1 = -INFINITY, l0 = 0.0f, l1 = 0.0f;

    // ldmatrix lane address components
    const uint32_t aQh = sQ + ((wid * 16 + (lane & 15)) * QS_STR + ((lane >> 4) << 3)) * 2;
    const uint32_t bKh = sK + (((lane & 7)) * QS_STR + (((lane >> 3) & 1) << 3)) * 2;
    const uint32_t bVrow = (lane & 15) * VS_STR * 2;

    for (int kt = 0; kt <= qb; kt++) {
        // ---- load + split K,V tile ----
#pragma unroll
        for (int it = 0; it < 8; it++) {
            int row = it * 8 + (tid >> 4);
            int c4  = tid & 15;
            const float* base = QKV + (size_t)(b * SEQ + kt * KT + row) * QKVW + EMB + g * HD;
            float4 kv = *(const float4*)(base + c4 * 4);
            float4 vv = *(const float4*)(base + KVDIM + c4 * 4);
            float kf[4] = {kv.x, kv.y, kv.z, kv.w};
            float vf[4] = {vv.x, vv.y, vv.z, vv.w};
#pragma unroll
            for (int j = 0; j < 4; j++) {
                __nv_bfloat16 khi = __float2bfloat16(kf[j]);
                Ks[row * QS_STR + c4 * 4 + j]      = khi;
                Ks[row * QS_STR + 64 + c4 * 4 + j] = __float2bfloat16(kf[j] - __bfloat162float(khi));
                __nv_bfloat16 vhi = __float2bfloat16(vf[j]);
                Vh[row * VS_STR + c4 * 4 + j] = vhi;
                Vl[row * VS_STR + c4 * 4 + j] = __float2bfloat16(vf[j] - __bfloat162float(vhi));
            }
        }
        __syncthreads();

        // ---- S = Q.K^T, split 3-term, fp32 accum ----
        float s[8][4];
#pragma unroll
        for (int n = 0; n < 8; n++)
#pragma unroll
            for (int q = 0; q < 4; q++) s[n][q] = 0.0f;

#pragma unroll
        for (int c = 0; c < 4; c++) {
            uint32_t a0[4], a1[4];
            ldsm_x4(a0, aQh + (c * 16) * 2);          // qh chunk c
            ldsm_x4(a1, aQh + (64 + c * 16) * 2);     // ql chunk c
#pragma unroll
            for (int n = 0; n < 8; n++) {
                uint32_t bb[2];
                ldsm_x2(bb, bKh + (n * 8 * QS_STR + c * 16) * 2);          // kh
                mma16816(s[n], a0, bb);
                mma16816(s[n], a1, bb);
            }
#pragma unroll
            for (int n = 0; n < 8; n++) {
                uint32_t bb[2];
                ldsm_x2(bb, bKh + (n * 8 * QS_STR + 64 + c * 16) * 2);     // kl
                mma16816(s[n], a0, bb);
            }
        }

        // ---- causal mask on diagonal tile ----
        if (kt == qb) {
            int r0 = wid * 16 + (lane >> 2);
#pragma unroll
            for (int n = 0; n < 8; n++) {
#pragma unroll
                for (int q = 0; q < 4; q++) {
                    int col = n * 8 + (lane & 3) * 2 + (q & 1);
                    int row = r0 + ((q >= 2) ? 8 : 0);
                    if (col > row) s[n][q] = -1e30f;
                }
            }
        }

        // ---- online softmax (base-2 domain) ----
        float mx0 = -INFINITY, mx1 = -INFINITY;
#pragma unroll
        for (int n = 0; n < 8; n++) {
            mx0 = fmaxf(mx0, fmaxf(s[n][0], s[n][1]));
            mx1 = fmaxf(mx1, fmaxf(s[n][2], s[n][3]));
        }
        mx0 = fmaxf(mx0, __shfl_xor_sync(0xffffffffu, mx0, 1));
        mx0 = fmaxf(mx0, __shfl_xor_sync(0xffffffffu, mx0, 2));
        mx1 = fmaxf(mx1, __shfl_xor_sync(0xffffffffu, mx1, 1));
        mx1 = fmaxf(mx1, __shfl_xor_sync(0xffffffffu, mx1, 2));
        float mn0 = fmaxf(m0, mx0), mn1 = fmaxf(m1, mx1);
        float sc0 = ex2f(m0 - mn0), sc1 = ex2f(m1 - mn1);
        l0 *= sc0; l1 *= sc1;
#pragma unroll
        for (int n = 0; n < 8; n++) {
            accO[n][0] *= sc0; accO[n][1] *= sc0;
            accO[n][2] *= sc1; accO[n][3] *= sc1;
        }
        m0 = mn0; m1 = mn1;

        uint32_t phx[8], phy[8], plx[8], ply[8];
#pragma unroll
        for (int n = 0; n < 8; n++) {
            float p0 = ex2f(s[n][0] - mn0);
            float p1 = ex2f(s[n][1] - mn0);
            float p2 = ex2f(s[n][2] - mn1);
            float p3 = ex2f(s[n][3] - mn1);
            l0 += p0 + p1; l1 += p2 + p3;
            __nv_bfloat162 h01 = __floats2bfloat162_rn(p0, p1);
            __nv_bfloat162 h23 = __floats2bfloat162_rn(p2, p3);
            phx[n] = *(uint32_t*)&h01;
            phy[n] = *(uint32_t*)&h23;
            plx[n] = pack_bf2(p0 - __bfloat162float(h01.x), p1 - __bfloat162float(h01.y));
            ply[n] = pack_bf2(p2 - __bfloat162float(h23.x), p3 - __bfloat162float(h23.y));
        }

        // ---- O += P.V, split 3-term ----
#pragma unroll
        for (int kc = 0; kc < 4; kc++) {
            uint32_t aH[4] = {phx[2 * kc], phy[2 * kc], phx[2 * kc + 1], phy[2 * kc + 1]};
            uint32_t aL[4] = {plx[2 * kc], ply[2 * kc], plx[2 * kc + 1], ply[2 * kc + 1]};
#pragma unroll
            for (int n = 0; n < 8; n++) {
                uint32_t bh[2], bl[2];
                ldsm_x2t(bh, sVh + (kc * 16 * VS_STR + n * 8) * 2 + bVrow);
                ldsm_x2t(bl, sVl + (kc * 16 * VS_STR + n * 8) * 2 + bVrow);
                mma16816(accO[n], aH, bh);
                mma16816(accO[n], aL, bh);
                mma16816(accO[n], aH, bl);
            }
        }
        __syncthreads();
    }

    // ---- finalize: reduce l across quad, normalize, store ----
    l0 += __shfl_xor_sync(0xffffffffu, l0, 1);
    l0 += __shfl_xor_sync(0xffffffffu, l0, 2);
    l1 += __shfl_xor_sync(0xffffffffu, l1, 1);
    l1 += __shfl_xor_sync(0xffffffffu, l1, 2);
    const float inv0 = 1.0f / l0, inv1 = 1.0f / l1;

    const int r0 = qb * QT + wid * 16 + (lane >> 2);
#pragma unroll
    for (int n = 0; n < 8; n++) {
        int col = n * 8 + (lane & 3) * 2;
        float* p0 = O + (size_t)(b * SEQ + r0) * EMB + h * HD + col;
        p0[0] = accO[n][0] * inv0; p0[1] = accO[n][1] * inv0;
        float* p1 = p0 + (size_t)8 * EMB;
        p1[0] = accO[n][2] * inv1; p1[1] = accO[n][3] * inv1;
    }
}

// ---------------- launch ----------------
extern "C" void kernel_launch(void* const* d_in, const int* in_sizes, int n_in,
                              void* d_out, int out_size)
{
    const float* x  = (const float*)d_in[0];
    const float* Wq = (const float*)d_in[1];
    const float* Wk = (const float*)d_in[2];
    const float* Wv = (const float*)d_in[3];
    const float* Wo = (const float*)d_in[4];
    float* out = (float*)d_out;

    float *QKV, *O;
    __nv_bfloat16 *A, *Bqkv, *Bo;
    cudaGetSymbolAddress((void**)&QKV, g_QKV);
    cudaGetSymbolAddress((void**)&O, g_O);
    cudaGetSymbolAddress((void**)&A, g_A);
    cudaGetSymbolAddress((void**)&Bqkv, g_Bqkv);
    cudaGetSymbolAddress((void**)&Bo, g_Bo);

    static bool attr_set = false;
    if (!attr_set) {
        cudaFuncSetAttribute(flash_hmma, cudaFuncAttributeMaxDynamicSharedMemorySize, 53248);
        attr_set = true;
    }

    // split-precision conversions
    conv_split_A<<<ROWS * EMB / 256, 256>>>(x, A);
    conv_split_Bt<<<EMB * EMB / 256, 256>>>(Wq, Bqkv, EMB);
    conv_split_Bt<<<EMB * KVDIM / 256, 256>>>(Wk, Bqkv + (size_t)EMB * K3, KVDIM);
    conv_split_Bt<<<EMB * KVDIM / 256, 256>>>(Wv, Bqkv + (size_t)(EMB + KVDIM) * K3, KVDIM);
    conv_split_Bt<<<EMB * EMB / 256, 256>>>(Wo, Bo, EMB);

    // fused QKV projection
    gemm_bf16<<<dim3(QKVW / 128, ROWS / 128), 256>>>(A, Bqkv, QKV, QKVW);

    // tensor-core flash attention
    flash_hmma<<<dim3(SEQ / QT, NH, BATCH), 128, 53248>>>(QKV, O);

    // output projection
    conv_split_A<<<ROWS * EMB / 256, 256>>>(O, A);
    gemm_bf16<<<dim3(EMB / 128, ROWS / 128), 256>>>(A, Bo, out, EMB);
}

// round 5
// speedup vs baseline: 4.1695x; 1.1812x over previous
#include <cuda_runtime.h>
#include <cuda_bf16.h>
#include <math.h>
#include <cstdint>

// Problem constants
#define BATCH 2
#define SEQ   2048
#define EMB   1024
#define NH    16
#define NKV   4
#define HD    64
#define KVDIM 256
#define ROWS  (BATCH*SEQ)     // 4096
#define K3    (3*EMB)         // 3072 : [Ah | Ah | Al] x [Bh | Bl | Bh]
#define QKVW  (EMB + 2*KVDIM) // 1536

// flash tiling
#define QT 64
#define KT 64
#define QS_STR 136            // bf16 units per row (272B), conflict-free
#define VS_STR 72             // 144B

#define QSCALE (0.125f * 1.44269504089f)   // 1/sqrt(64) * log2(e)

// ---------------- scratch ----------------
__device__ __nv_bfloat16 g_QKVh[ROWS * QKVW];   // split QKV output (hi)
__device__ __nv_bfloat16 g_QKVl[ROWS * QKVW];   // split QKV output (lo)
__device__ __nv_bfloat16 g_A   [ROWS * K3];     // split activations (x, then attn-out)
__device__ __nv_bfloat16 g_Bqkv[QKVW * K3];
__device__ __nv_bfloat16 g_Bo  [EMB  * K3];

// ---------------- helpers ----------------
__device__ __forceinline__ uint32_t smem_u32(const void* p) {
    uint32_t a;
    asm("{ .reg .u64 t; cvta.to.shared.u64 t, %1; cvt.u32.u64 %0, t; }" : "=r"(a) : "l"(p));
    return a;
}
__device__ __forceinline__ void ldsm_x4(uint32_t* r, uint32_t addr) {
    asm volatile("ldmatrix.sync.aligned.m8n8.x4.shared.b16 {%0,%1,%2,%3}, [%4];"
        : "=r"(r[0]), "=r"(r[1]), "=r"(r[2]), "=r"(r[3]) : "r"(addr));
}
__device__ __forceinline__ void ldsm_x2(uint32_t* r, uint32_t addr) {
    asm volatile("ldmatrix.sync.aligned.m8n8.x2.shared.b16 {%0,%1}, [%2];"
        : "=r"(r[0]), "=r"(r[1]) : "r"(addr));
}
__device__ __forceinline__ void ldsm_x2t(uint32_t* r, uint32_t addr) {
    asm volatile("ldmatrix.sync.aligned.m8n8.x2.trans.shared.b16 {%0,%1}, [%2];"
        : "=r"(r[0]), "=r"(r[1]) : "r"(addr));
}
__device__ __forceinline__ void mma16816(float* c, const uint32_t* a, const uint32_t* b) {
    asm volatile("mma.sync.aligned.m16n8k16.row.col.f32.bf16.bf16.f32 "
        "{%0,%1,%2,%3}, {%4,%5,%6,%7}, {%8,%9}, {%0,%1,%2,%3};"
        : "+f"(c[0]), "+f"(c[1]), "+f"(c[2]), "+f"(c[3])
        : "r"(a[0]), "r"(a[1]), "r"(a[2]), "r"(a[3]), "r"(b[0]), "r"(b[1]));
}
__device__ __forceinline__ float ex2f(float x) {
    float y;
    asm("ex2.approx.ftz.f32 %0, %1;" : "=f"(y) : "f"(x));
    return y;
}
__device__ __forceinline__ uint32_t pack_bf2(float a, float b) {
    __nv_bfloat162 t = __floats2bfloat162_rn(a, b);
    return *(uint32_t*)&t;
}
#define CP_ASYNC16(dst, src) \
    asm volatile("cp.async.cg.shared.global [%0], [%1], 16;" :: "r"(dst), "l"(src))
#define CP_COMMIT() asm volatile("cp.async.commit_group;" ::: "memory")
#define CP_WAIT1()  asm volatile("cp.async.wait_group 1;" ::: "memory")
#define CP_WAIT0()  asm volatile("cp.async.wait_group 0;" ::: "memory")

// ---------------- split-precision conversion kernels ----------------
__global__ __launch_bounds__(256) void conv_split_A(const float* __restrict__ X,
                                                    __nv_bfloat16* __restrict__ A)
{
    int idx = blockIdx.x * 256 + threadIdx.x;
    int r = idx >> 10, c = idx & 1023;
    float v = X[idx];
    __nv_bfloat16 h = __float2bfloat16(v);
    __nv_bfloat16 l = __float2bfloat16(v - __bfloat162float(h));
    size_t base = (size_t)r * K3;
    A[base + c] = h;
    A[base + 1024 + c] = h;
    A[base + 2048 + c] = l;
}
__global__ __launch_bounds__(256) void conv_split_Bt(const float* __restrict__ W,
                                                     __nv_bfloat16* __restrict__ Bt, int N)
{
    int idx = blockIdx.x * 256 + threadIdx.x;
    int n = idx >> 10, k = idx & 1023;
    float v = W[(size_t)k * N + n];
    __nv_bfloat16 h = __float2bfloat16(v);
    __nv_bfloat16 l = __float2bfloat16(v - __bfloat162float(h));
    size_t base = (size_t)n * K3;
    Bt[base + k] = h;
    Bt[base + 1024 + k] = l;
    Bt[base + 2048 + k] = h;
}

// ---------------- pipelined HMMA bf16 GEMM ----------------
// CTA tile 128x128, BK=64, 2-stage cp.async. 256 threads = 8 warps (2x4).
// mode 0: fp32 C store. mode 1: split bf16 hi/lo store, cols < EMB scaled by QSCALE.
__global__ __launch_bounds__(256) void gemm_bf16(
    const __nv_bfloat16* __restrict__ A,
    const __nv_bfloat16* __restrict__ Bt,
    float* __restrict__ C,
    __nv_bfloat16* __restrict__ Ch,
    __nv_bfloat16* __restrict__ Cl,
    int N, int mode)
{
    extern __shared__ __align__(128) char smem_g[];   // 2 stages x (16KB A | 16KB B)

    const int tid  = threadIdx.x;
    const int lane = tid & 31, wid = tid >> 5;
    const int wm = wid & 1;
    const int wn = wid >> 1;
    const int bx = blockIdx.x, by = blockIdx.y;

    const __nv_bfloat16* Ab = A  + (size_t)by * 128 * K3;
    const __nv_bfloat16* Bb = Bt + (size_t)bx * 128 * K3;

    float acc[4][4][4];
#pragma unroll
    for (int i = 0; i < 4; i++)
#pragma unroll
        for (int j = 0; j < 4; j++)
#pragma unroll
            for (int q = 0; q < 4; q++) acc[i][j][q] = 0.0f;

    const int a_r = wm * 64 + (lane & 15);
    const int a_c = (lane >> 4);
    const int b_r = wn * 32 + (lane & 7);
    const int b_c = ((lane >> 3) & 1);

    const int row_ld = tid >> 3, c16_ld = tid & 7;   // each thread: 4 rows apart x 32
    const uint32_t sw_ld = ((c16_ld ^ (row_ld & 7)) * 16);

    // issue loads for one chunk into stage s
    auto issue = [&](int ch, int s) {
        const int k0 = ch * 64;
        char* sA = smem_g + s * 32768;
        char* sB = sA + 16384;
#pragma unroll
        for (int p = 0; p < 4; p++) {
            int row = row_ld + p * 32;
            uint32_t sw = row * 128 + sw_ld;
            CP_ASYNC16(smem_u32(sA + sw), (const char*)(Ab + (size_t)row * K3 + k0 + c16_ld * 8));
            CP_ASYNC16(smem_u32(sB + sw), (const char*)(Bb + (size_t)row * K3 + k0 + c16_ld * 8));
        }
        CP_COMMIT();
    };

    const int NCH = K3 / 64;
    issue(0, 0);

    for (int ch = 0; ch < NCH; ch++) {
        const int s = ch & 1;
        if (ch + 1 < NCH) { issue(ch + 1, (ch + 1) & 1); CP_WAIT1(); }
        else              { CP_WAIT0(); }
        __syncthreads();

        const uint32_t sA_u = smem_u32(smem_g + s * 32768);
        const uint32_t sB_u = sA_u + 16384;
#pragma unroll
        for (int ks = 0; ks < 4; ks++) {
            uint32_t a[4][4], b[4][2];
#pragma unroll
            for (int i = 0; i < 4; i++) {
                int row = a_r + i * 16;
                int chk = a_c + ks * 2;
                ldsm_x4(a[i], sA_u + row * 128 + ((chk ^ (row & 7)) * 16));
            }
#pragma unroll
            for (int j = 0; j < 4; j++) {
                int row = b_r + j * 8;
                int chk = b_c + ks * 2;
                ldsm_x2(b[j], sB_u + row * 128 + ((chk ^ (row & 7)) * 16));
            }
#pragma unroll
            for (int i = 0; i < 4; i++)
#pragma unroll
                for (int j = 0; j < 4; j++)
                    mma16816(acc[i][j], a[i], b[j]);
        }
        __syncthreads();
    }

    // epilogue
#pragma unroll
    for (int i = 0; i < 4; i++)
#pragma unroll
        for (int j = 0; j < 4; j++) {
            int r0  = by * 128 + wm * 64 + i * 16 + (lane >> 2);
            int col = bx * 128 + wn * 32 + j * 8 + (lane & 3) * 2;
            if (mode == 0) {
                float* p0 = C + (size_t)r0 * N + col;
                p0[0] = acc[i][j][0]; p0[1] = acc[i][j][1];
                float* p1 = p0 + (size_t)8 * N;
                p1[0] = acc[i][j][2]; p1[1] = acc[i][j][3];
            } else {
                float sc = (col < EMB) ? QSCALE : 1.0f;
                float v0 = acc[i][j][0] * sc, v1 = acc[i][j][1] * sc;
                float v2 = acc[i][j][2] * sc, v3 = acc[i][j][3] * sc;
                __nv_bfloat162 h01 = __floats2bfloat162_rn(v0, v1);
                __nv_bfloat162 h23 = __floats2bfloat162_rn(v2, v3);
                *(uint32_t*)(Ch + (size_t)r0 * N + col)       = *(uint32_t*)&h01;
                *(uint32_t*)(Ch + (size_t)(r0 + 8) * N + col) = *(uint32_t*)&h23;
                *(uint32_t*)(Cl + (size_t)r0 * N + col) =
                    pack_bf2(v0 - __bfloat162float(h01.x), v1 - __bfloat162float(h01.y));
                *(uint32_t*)(Cl + (size_t)(r0 + 8) * N + col) =
                    pack_bf2(v2 - __bfloat162float(h23.x), v3 - __bfloat162float(h23.y));
            }
        }
}

// ---------------- HMMA flash attention (pre-split inputs, split A output) ----------------
// grid (SEQ/64, NH, BATCH), 128 threads = 4 warps x 16 query rows.
__global__ __launch_bounds__(128) void flash_hmma(
    const __nv_bfloat16* __restrict__ QKVh,
    const __nv_bfloat16* __restrict__ QKVl,
    __nv_bfloat16* __restrict__ Aout)
{
    extern __shared__ __align__(16) char smem[];
    __nv_bfloat16* Qs = (__nv_bfloat16*)smem;                   // 64 x 136 = 17408 B
    __nv_bfloat16* Ks = (__nv_bfloat16*)(smem + 17408);         // 17408 B
    __nv_bfloat16* Vh = (__nv_bfloat16*)(smem + 34816);         //  9216 B
    __nv_bfloat16* Vl = (__nv_bfloat16*)(smem + 44032);         //  9216 B

    const int qb = blockIdx.x, h = blockIdx.y, b = blockIdx.z;
    const int g = h >> 2;
    const int tid = threadIdx.x, lane = tid & 31, wid = tid >> 5;
    const uint32_t sQ = smem_u32(Qs), sK = smem_u32(Ks);
    const uint32_t sVh = smem_u32(Vh), sVl = smem_u32(Vl);

    // ---- Q tile: pure copy of pre-split, pre-scaled bf16 ----
    {
        const int row = (tid >> 4);          // +8 per iter
        const int c4  = tid & 15;
        const int hi  = (c4 < 8);
        const __nv_bfloat16* src = (hi ? QKVh : QKVl);
        const int co = (hi ? c4 : c4 - 8) * 8;
        const int dst_col = (hi ? co : 64 + co);
#pragma unroll
        for (int it = 0; it < 8; it++) {
            int r = it * 8 + row;
            *(uint4*)(Qs + r * QS_STR + dst_col) =
                *(const uint4*)(src + (size_t)(b * SEQ + qb * QT + r) * QKVW + h * HD + co);
        }
    }
    __syncthreads();

    float accO[8][4];
#pragma unroll
    for (int n = 0; n < 8; n++)
#pragma unroll
        for (int q = 0; q < 4; q++) accO[n][q] = 0.0f;
    float m0 = -INFINITY, m1 = -INFINITY, l0 = 0.0f, l1 = 0.0f;

    const uint32_t aQh = sQ + ((wid * 16 + (lane & 15)) * QS_STR + ((lane >> 4) << 3)) * 2;
    const uint32_t bKh = sK + (((lane & 7)) * QS_STR + (((lane >> 3) & 1) << 3)) * 2;
    const uint32_t bVrow = (lane & 15) * VS_STR * 2;

    for (int kt = 0; kt <= qb; kt++) {
        // ---- K,V tile copies ----
        {
            const int row = (tid >> 4);
            const int c4  = tid & 15;
            const int hi  = (c4 < 8);
            const __nv_bfloat16* src = (hi ? QKVh : QKVl);
            const int co = (hi ? c4 : c4 - 8) * 8;
            const int kdst = (hi ? co : 64 + co);
            __nv_bfloat16* vdst_buf = (hi ? Vh : Vl);
#pragma unroll
            for (int it = 0; it < 8; it++) {
                int r = it * 8 + row;
                size_t base = (size_t)(b * SEQ + kt * KT + r) * QKVW + EMB + g * HD;
                *(uint4*)(Ks + r * QS_STR + kdst) = *(const uint4*)(src + base + co);
                *(uint4*)(vdst_buf + r * VS_STR + co) = *(const uint4*)(src + base + KVDIM + co);
            }
        }
        __syncthreads();

        // ---- S = Q.K^T, 3-term split ----
        float s[8][4];
#pragma unroll
        for (int n = 0; n < 8; n++)
#pragma unroll
            for (int q = 0; q < 4; q++) s[n][q] = 0.0f;

#pragma unroll
        for (int c = 0; c < 4; c++) {
            uint32_t a0[4], a1[4];
            ldsm_x4(a0, aQh + (c * 16) * 2);
            ldsm_x4(a1, aQh + (64 + c * 16) * 2);
#pragma unroll
            for (int n = 0; n < 8; n++) {
                uint32_t bb[2];
                ldsm_x2(bb, bKh + (n * 8 * QS_STR + c * 16) * 2);
                mma16816(s[n], a0, bb);
                mma16816(s[n], a1, bb);
            }
#pragma unroll
            for (int n = 0; n < 8; n++) {
                uint32_t bb[2];
                ldsm_x2(bb, bKh + (n * 8 * QS_STR + 64 + c * 16) * 2);
                mma16816(s[n], a0, bb);
            }
        }

        // ---- causal mask ----
        if (kt == qb) {
            int r0 = wid * 16 + (lane >> 2);
#pragma unroll
            for (int n = 0; n < 8; n++) {
#pragma unroll
                for (int q = 0; q < 4; q++) {
                    int col = n * 8 + (lane & 3) * 2 + (q & 1);
                    int row = r0 + ((q >= 2) ? 8 : 0);
                    if (col > row) s[n][q] = -1e30f;
                }
            }
        }

        // ---- online softmax (base-2) ----
        float mx0 = -INFINITY, mx1 = -INFINITY;
#pragma unroll
        for (int n = 0; n < 8; n++) {
            mx0 = fmaxf(mx0, fmaxf(s[n][0], s[n][1]));
            mx1 = fmaxf(mx1, fmaxf(s[n][2], s[n][3]));
        }
        mx0 = fmaxf(mx0, __shfl_xor_sync(0xffffffffu, mx0, 1));
        mx0 = fmaxf(mx0, __shfl_xor_sync(0xffffffffu, mx0, 2));
        mx1 = fmaxf(mx1, __shfl_xor_sync(0xffffffffu, mx1, 1));
        mx1 = fmaxf(mx1, __shfl_xor_sync(0xffffffffu, mx1, 2));
        float mn0 = fmaxf(m0, mx0), mn1 = fmaxf(m1, mx1);
        float sc0 = ex2f(m0 - mn0), sc1 = ex2f(m1 - mn1);
        l0 *= sc0; l1 *= sc1;
#pragma unroll
        for (int n = 0; n < 8; n++) {
            accO[n][0] *= sc0; accO[n][1] *= sc0;
            accO[n][2] *= sc1; accO[n][3] *= sc1;
        }
        m0 = mn0; m1 = mn1;

        uint32_t phx[8], phy[8], plx[8], ply[8];
#pragma unroll
        for (int n = 0; n < 8; n++) {
            float p0 = ex2f(s[n][0] - mn0);
            float p1 = ex2f(s[n][1] - mn0);
            float p2 = ex2f(s[n][2] - mn1);
            float p3 = ex2f(s[n][3] - mn1);
            l0 += p0 + p1; l1 += p2 + p3;
            __nv_bfloat162 h01 = __floats2bfloat162_rn(p0, p1);
            __nv_bfloat162 h23 = __floats2bfloat162_rn(p2, p3);
            phx[n] = *(uint32_t*)&h01;
            phy[n] = *(uint32_t*)&h23;
            plx[n] = pack_bf2(p0 - __bfloat162float(h01.x), p1 - __bfloat162float(h01.y));
            ply[n] = pack_bf2(p2 - __bfloat162float(h23.x), p3 - __bfloat162float(h23.y));
        }

        // ---- O += P.V, 3-term split ----
#pragma unroll
        for (int kc = 0; kc < 4; kc++) {
            uint32_t aH[4] = {phx[2 * kc], phy[2 * kc], phx[2 * kc + 1], phy[2 * kc + 1]};
            uint32_t aL[4] = {plx[2 * kc], ply[2 * kc], plx[2 * kc + 1], ply[2 * kc + 1]};
#pragma unroll
            for (int n = 0; n < 8; n++) {
                uint32_t bh[2], bl[2];
                ldsm_x2t(bh, sVh + (kc * 16 * VS_STR + n * 8) * 2 + bVrow);
                ldsm_x2t(bl, sVl + (kc * 16 * VS_STR + n * 8) * 2 + bVrow);
                mma16816(accO[n], aH, bh);
                mma16816(accO[n], aL, bh);
                mma16816(accO[n], aH, bl);
            }
        }
        __syncthreads();
    }

    // ---- finalize: normalize + split store into A layout [hi|hi|lo] ----
    l0 += __shfl_xor_sync(0xffffffffu, l0, 1);
    l0 += __shfl_xor_sync(0xffffffffu, l0, 2);
    l1 += __shfl_xor_sync(0xffffffffu, l1, 1);
    l1 += __shfl_xor_sync(0xffffffffu, l1, 2);
    const float inv0 = 1.0f / l0, inv1 = 1.0f / l1;

    const int r0 = qb * QT + wid * 16 + (lane >> 2);
#pragma unroll
    for (int n = 0; n < 8; n++) {
        int col = h * HD + n * 8 + (lane & 3) * 2;
        float v0 = accO[n][0] * inv0, v1 = accO[n][1] * inv0;
        float v2 = accO[n][2] * inv1, v3 = accO[n][3] * inv1;
        __nv_bfloat162 h01 = __floats2bfloat162_rn(v0, v1);
        __nv_bfloat162 h23 = __floats2bfloat162_rn(v2, v3);
        uint32_t lo01 = pack_bf2(v0 - __bfloat162float(h01.x), v1 - __bfloat162float(h01.y));
        uint32_t lo23 = pack_bf2(v2 - __bfloat162float(h23.x), v3 - __bfloat162float(h23.y));
        size_t ra = (size_t)(b * SEQ + r0) * K3;
        size_t rb = (size_t)(b * SEQ + r0 + 8) * K3;
        *(uint32_t*)(Aout + ra + col)        = *(uint32_t*)&h01;
        *(uint32_t*)(Aout + ra + 1024 + col) = *(uint32_t*)&h01;
        *(uint32_t*)(Aout + ra + 2048 + col) = lo01;
        *(uint32_t*)(Aout + rb + col)        = *(uint32_t*)&h23;
        *(uint32_t*)(Aout + rb + 1024 + col) = *(uint32_t*)&h23;
        *(uint32_t*)(Aout + rb + 2048 + col) = lo23;
    }
}

// ---------------- launch ----------------
extern "C" void kernel_launch(void* const* d_in, const int* in_sizes, int n_in,
                              void* d_out, int out_size)
{
    const float* x  = (const float*)d_in[0];
    const float* Wq = (const float*)d_in[1];
    const float* Wk = (const float*)d_in[2];
    const float* Wv = (const float*)d_in[3];
    const float* Wo = (const float*)d_in[4];
    float* out = (float*)d_out;

    __nv_bfloat16 *QKVh, *QKVl, *A, *Bqkv, *Bo;
    cudaGetSymbolAddress((void**)&QKVh, g_QKVh);
    cudaGetSymbolAddress((void**)&QKVl, g_QKVl);
    cudaGetSymbolAddress((void**)&A, g_A);
    cudaGetSymbolAddress((void**)&Bqkv, g_Bqkv);
    cudaGetSymbolAddress((void**)&Bo, g_Bo);

    static bool attr_set = false;
    if (!attr_set) {
        cudaFuncSetAttribute(flash_hmma, cudaFuncAttributeMaxDynamicSharedMemorySize, 53248);
        cudaFuncSetAttribute(gemm_bf16, cudaFuncAttributeMaxDynamicSharedMemorySize, 65536);
        attr_set = true;
    }

    // split-precision conversions
    conv_split_A<<<ROWS * EMB / 256, 256>>>(x, A);
    conv_split_Bt<<<EMB * EMB / 256, 256>>>(Wq, Bqkv, EMB);
    conv_split_Bt<<<EMB * KVDIM / 256, 256>>>(Wk, Bqkv + (size_t)EMB * K3, KVDIM);
    conv_split_Bt<<<EMB * KVDIM / 256, 256>>>(Wv, Bqkv + (size_t)(EMB + KVDIM) * K3, KVDIM);
    conv_split_Bt<<<EMB * EMB / 256, 256>>>(Wo, Bo, EMB);

    // fused QKV projection -> split bf16 (Q pre-scaled)
    gemm_bf16<<<dim3(QKVW / 128, ROWS / 128), 256, 65536>>>(
        A, Bqkv, nullptr, QKVh, QKVl, QKVW, 1);

    // flash attention -> split A layout
    flash_hmma<<<dim3(SEQ / QT, NH, BATCH), 128, 53248>>>(QKVh, QKVl, A);

    // output projection -> fp32 out
    gemm_bf16<<<dim3(EMB / 128, ROWS / 128), 256, 65536>>>(
        A, Bo, out, nullptr, nullptr, EMB, 0);
}